// round 1
// baseline (speedup 1.0000x reference)
#include <cuda_runtime.h>
#include <cuda_bf16.h>
#include <math.h>

// ---------------- problem constants ----------------
#define NMAX 50176
#define EMAX 800000
#define H    128
#define HEADS 8
#define HD   16
#define OUTD 19

// ---------------- scratch (__device__ globals: allowed) ----------------
__device__ float    g_h0[NMAX * H];
__device__ float    g_hl[NMAX * H];
__device__ float    g_aggG[NMAX * H];
__device__ float    g_h1[NMAX * H];
__device__ float    g_cqkv[NMAX * 64];
__device__ float    g_q[NMAX * H];
__device__ float    g_k[NMAX * H];
__device__ float    g_v[NMAX * H];
__device__ float    g_aggA[NMAX * H];
__device__ float    g_h2[NMAX * H];
__device__ float    g_deg[NMAX];
__device__ unsigned g_menc[NMAX * HEADS];
__device__ float    g_mf[NMAX * HEADS];
__device__ float    g_den[NMAX * HEADS];
__device__ float    g_score[(size_t)EMAX * HEADS];
__device__ float    g_w64[H * 64];
__device__ float    g_b64[64];

// order-preserving float<->uint encoding for atomicMax
__device__ __forceinline__ unsigned enc_f(float f) {
    unsigned u = __float_as_uint(f);
    return (u & 0x80000000u) ? ~u : (u | 0x80000000u);
}
__device__ __forceinline__ float dec_f(unsigned u) {
    return (u & 0x80000000u) ? __uint_as_float(u & 0x7FFFFFFFu) : __uint_as_float(~u);
}

// ---------------- init kernels ----------------
__global__ void k_init(float* deg, unsigned* menc, float* den, int N) {
    int i = blockIdx.x * blockDim.x + threadIdx.x;
    if (i < N * HEADS) { menc[i] = 0u; den[i] = 0.f; }
    if (i < N) deg[i] = 1.0f;  // self loop
}

__global__ void k_embed(const int* __restrict__ x, const float* __restrict__ emb,
                        float* __restrict__ h0, float* __restrict__ aggA, int N) {
    int i = blockIdx.x * blockDim.x + threadIdx.x;  // over N*32 (float4)
    if (i >= N * 32) return;
    int n = i >> 5, c4 = i & 31;
    int tok = __ldg(&x[n * 11]);
    float4 v = ((const float4*)(emb + (size_t)tok * H))[c4];
    ((float4*)h0)[i] = v;
    ((float4*)aggA)[i] = make_float4(0.f, 0.f, 0.f, 0.f);
}

__global__ void k_deg(const int* __restrict__ ei, float* __restrict__ deg, int E) {
    int e = blockIdx.x * blockDim.x + threadIdx.x;
    if (e >= E) return;
    atomicAdd(&deg[ei[E + e]], 1.0f);
}

__global__ void k_dinv(float* deg, int N) {
    int i = blockIdx.x * blockDim.x + threadIdx.x;
    if (i < N) deg[i] = rsqrtf(deg[i]);  // deg>=1 always
}

// ---------------- generic small GEMM: out[r,c] = sum_k in[r,k]*W[k,c] (+b) ----------------
template <int IN, int OUT, bool RELU>
__global__ void k_gemm(const float* __restrict__ in, int in_stride, int in_off,
                       const float* __restrict__ W, const float* __restrict__ B,
                       float* __restrict__ out, int nrows, int rpb) {
    __shared__ float rows_s[4][IN];
    const int tid = threadIdx.x;  // blockDim == OUT
    int r0 = blockIdx.x * rpb;
    int r1 = min(r0 + rpb, nrows);
    float bias = B ? B[tid] : 0.f;
    constexpr int V = IN / 4;
    for (int r = r0; r < r1; r += 4) {
        __syncthreads();
        for (int i = tid; i < 4 * V; i += OUT) {
            int j = i / V, idx = i % V;
            float4 val = (r + j < r1)
                ? ((const float4*)(in + (size_t)(r + j) * in_stride + in_off))[idx]
                : make_float4(0.f, 0.f, 0.f, 0.f);
            ((float4*)rows_s[j])[idx] = val;
        }
        __syncthreads();
        float a0 = bias, a1 = bias, a2 = bias, a3 = bias;
#pragma unroll 16
        for (int k2 = 0; k2 < IN; k2++) {
            float w = __ldg(W + k2 * OUT + tid);
            a0 += rows_s[0][k2] * w;
            a1 += rows_s[1][k2] * w;
            a2 += rows_s[2][k2] * w;
            a3 += rows_s[3][k2] * w;
        }
        if (r + 0 < r1) out[(size_t)(r + 0) * OUT + tid] = RELU ? fmaxf(a0, 0.f) : a0;
        if (r + 1 < r1) out[(size_t)(r + 1) * OUT + tid] = RELU ? fmaxf(a1, 0.f) : a1;
        if (r + 2 < r1) out[(size_t)(r + 2) * OUT + tid] = RELU ? fmaxf(a2, 0.f) : a2;
        if (r + 3 < r1) out[(size_t)(r + 3) * OUT + tid] = RELU ? fmaxf(a3, 0.f) : a3;
    }
}

// ---------------- GCN ----------------
__global__ void k_selfmsg(const float* __restrict__ hl, const float* __restrict__ dinv,
                          float* __restrict__ aggG, int N) {
    int i = blockIdx.x * blockDim.x + threadIdx.x;  // N*32
    if (i >= N * 32) return;
    int n = i >> 5;
    float di = dinv[n];
    float s = di * di;
    float4 v = ((const float4*)hl)[i];
    v.x *= s; v.y *= s; v.z *= s; v.w *= s;
    ((float4*)aggG)[i] = v;
}

__global__ void k_gcn_scatter(const int* __restrict__ ei, const float* __restrict__ hl,
                              const float* __restrict__ dinv, float* __restrict__ aggG, int E) {
    long long t = (long long)blockIdx.x * blockDim.x + threadIdx.x;  // E*32
    int e = (int)(t >> 5);
    if (e >= E) return;
    int lane = (int)t & 31;
    int s = ei[e], d = ei[E + e];
    float nm = dinv[s] * dinv[d];
    float4 m = ((const float4*)(hl + (size_t)s * H))[lane];
    m.x *= nm; m.y *= nm; m.z *= nm; m.w *= nm;
    atomicAdd(((float4*)(aggG + (size_t)d * H)) + lane, m);
}

__global__ void k_bias_relu(const float* __restrict__ aggG, const float* __restrict__ b,
                            float* __restrict__ h1, int N) {
    int i = blockIdx.x * blockDim.x + threadIdx.x;  // N*32
    if (i >= N * 32) return;
    int c4 = i & 31;
    float4 bb = ((const float4*)b)[c4];
    float4 v = ((const float4*)aggG)[i];
    v.x = fmaxf(v.x + bb.x, 0.f);
    v.y = fmaxf(v.y + bb.y, 0.f);
    v.z = fmaxf(v.z + bb.z, 0.f);
    v.w = fmaxf(v.w + bb.w, 0.f);
    ((float4*)h1)[i] = v;
}

// pack [qd_w | kvd_w] into one 128x64 weight, biases too
__global__ void k_packw(const float* __restrict__ qd_w, const float* __restrict__ qd_b,
                        const float* __restrict__ kvd_w, const float* __restrict__ kvd_b,
                        float* __restrict__ w64, float* __restrict__ b64) {
    int i = blockIdx.x * blockDim.x + threadIdx.x;
    if (i < H * 64) {
        int k2 = i >> 6, c = i & 63;
        w64[i] = (c < 32) ? qd_w[k2 * 32 + c] : kvd_w[k2 * 32 + (c - 32)];
    }
    if (i < 64) b64[i] = (i < 32) ? qd_b[i] : kvd_b[i - 32];
}

// ---------------- attention ----------------
__global__ void k_score(const int* __restrict__ ei, const float* __restrict__ q,
                        const float* __restrict__ kk, float* __restrict__ score,
                        unsigned* __restrict__ menc, int E) {
    int t = blockIdx.x * blockDim.x + threadIdx.x;  // E*8
    if (t >= E * HEADS) return;
    int e = t >> 3, h = t & 7;
    int s = ei[e], d = ei[E + e];
    const float4* qp = (const float4*)(q + (size_t)d * H + h * HD);
    const float4* kp = (const float4*)(kk + (size_t)s * H + h * HD);
    float acc = 0.f;
#pragma unroll
    for (int i = 0; i < 4; i++) {
        float4 a = qp[i], b = kp[i];
        acc += a.x * b.x + a.y * b.y + a.z * b.z + a.w * b.w;
    }
    acc *= 0.25f;  // 1/sqrt(16)
    score[t] = acc;
    atomicMax(menc + (size_t)d * HEADS + h, enc_f(acc));
}

__global__ void k_decode(const unsigned* __restrict__ menc, float* __restrict__ mf, int N) {
    int i = blockIdx.x * blockDim.x + threadIdx.x;
    if (i >= N * HEADS) return;
    unsigned u = menc[i];
    mf[i] = (u == 0u) ? 0.f : dec_f(u);
}

__global__ void k_exp(const int* __restrict__ ei, float* __restrict__ score,
                      const float* __restrict__ mf, float* __restrict__ den, int E) {
    int t = blockIdx.x * blockDim.x + threadIdx.x;  // E*8
    if (t >= E * HEADS) return;
    int e = t >> 3, h = t & 7;
    int d = ei[E + e];
    float ex = expf(score[t] - mf[(size_t)d * HEADS + h]);
    score[t] = ex;
    atomicAdd(den + (size_t)d * HEADS + h, ex);
}

__global__ void k_agg(const int* __restrict__ ei, const float* __restrict__ score,
                      const float* __restrict__ den, const float* __restrict__ v,
                      float* __restrict__ aggA, int E) {
    long long t = (long long)blockIdx.x * blockDim.x + threadIdx.x;  // E*32
    int e = (int)(t >> 5);
    if (e >= E) return;
    int lane = (int)t & 31;
    int h = lane >> 2;
    int s = ei[e], d = ei[E + e];
    float ex = score[(size_t)e * HEADS + h];
    float dn = den[(size_t)d * HEADS + h];
    float alpha = ex / fmaxf(dn, 1e-16f);
    float4 vv = ((const float4*)(v + (size_t)s * H))[lane];
    vv.x *= alpha; vv.y *= alpha; vv.z *= alpha; vv.w *= alpha;
    atomicAdd(((float4*)(aggA + (size_t)d * H)) + lane, vv);
}

// ---------------- output proj + residual + LN + relu ----------------
__global__ void k_out_ln(const float* __restrict__ agg, const float* __restrict__ res,
                         const float* __restrict__ ow, const float* __restrict__ ob,
                         const float* __restrict__ lg, const float* __restrict__ lb,
                         float* __restrict__ h2, int nrows, int rpb) {
    __shared__ float rows_s[4][H];
    __shared__ float red[8];
    const int tid = threadIdx.x;  // 128
    int r0 = blockIdx.x * rpb;
    int r1 = min(r0 + rpb, nrows);
    float bias = ob[tid], gg = lg[tid], bb = lb[tid];
    for (int r = r0; r < r1; r += 4) {
        __syncthreads();
        for (int i = tid; i < 4 * 32; i += H) {
            int j = i >> 5, idx = i & 31;
            float4 val = (r + j < r1) ? ((const float4*)(agg + (size_t)(r + j) * H))[idx]
                                      : make_float4(0.f, 0.f, 0.f, 0.f);
            ((float4*)rows_s[j])[idx] = val;
        }
        __syncthreads();
        float a[4] = {bias, bias, bias, bias};
#pragma unroll 16
        for (int k2 = 0; k2 < H; k2++) {
            float w = __ldg(ow + k2 * H + tid);
            a[0] += rows_s[0][k2] * w;
            a[1] += rows_s[1][k2] * w;
            a[2] += rows_s[2][k2] * w;
            a[3] += rows_s[3][k2] * w;
        }
#pragma unroll
        for (int j = 0; j < 4; j++) {
            if (r + j >= r1) break;  // uniform across block
            float t = a[j] + res[(size_t)(r + j) * H + tid];
            // block mean
            float s1 = t;
            for (int o = 16; o > 0; o >>= 1) s1 += __shfl_down_sync(~0u, s1, o);
            __syncthreads();
            if ((tid & 31) == 0) red[tid >> 5] = s1;
            __syncthreads();
            float mu = (red[0] + red[1] + red[2] + red[3]) * (1.f / 128.f);
            // block var (two-pass, matches reference)
            float dvar = (t - mu) * (t - mu);
            for (int o = 16; o > 0; o >>= 1) dvar += __shfl_down_sync(~0u, dvar, o);
            __syncthreads();
            if ((tid & 31) == 0) red[4 + (tid >> 5)] = dvar;
            __syncthreads();
            float var = (red[4] + red[5] + red[6] + red[7]) * (1.f / 128.f);
            float inv = rsqrtf(var + 1e-5f);
            h2[(size_t)(r + j) * H + tid] = fmaxf((t - mu) * inv * gg + bb, 0.f);
        }
    }
}

// ---------------- fused pooling + final FC (batch sorted -> binary search) ----------------
__device__ __forceinline__ int lower_bound(const int* __restrict__ a, int n, int key) {
    int lo = 0, hi = n;
    while (lo < hi) {
        int mid = (lo + hi) >> 1;
        if (a[mid] < key) lo = mid + 1; else hi = mid;
    }
    return lo;
}

__global__ void k_pool_fc(const float* __restrict__ h2, const int* __restrict__ batch,
                          const float* __restrict__ fc_w, const float* __restrict__ fc_b,
                          float* __restrict__ out, int N) {
    int g = blockIdx.x;
    int tid = threadIdx.x;  // 128
    __shared__ float pool[H];
    int lo = lower_bound(batch, N, g);
    int hi = lower_bound(batch, N, g + 1);
    float acc = 0.f;
    for (int n = lo; n < hi; n++) acc += h2[(size_t)n * H + tid];
    pool[tid] = acc;
    __syncthreads();
    if (tid < OUTD) {
        float o = fc_b[tid];
#pragma unroll 16
        for (int c = 0; c < H; c++) o += pool[c] * __ldg(fc_w + c * OUTD + tid);
        out[(size_t)g * OUTD + tid] = o;
    }
}

// ---------------- host ----------------
static inline int ceil_div(long long a, int b) { return (int)((a + b - 1) / b); }

extern "C" void kernel_launch(void* const* d_in, const int* in_sizes, int n_in,
                              void* d_out, int out_size) {
    const int*   x        = (const int*)d_in[0];
    const int*   ei       = (const int*)d_in[1];
    const int*   batch    = (const int*)d_in[2];
    const float* node_emb = (const float*)d_in[3];
    const float* gcn_w    = (const float*)d_in[4];
    const float* gcn_b    = (const float*)d_in[5];
    const float* qd_w     = (const float*)d_in[6];
    const float* qd_b     = (const float*)d_in[7];
    const float* qu_w     = (const float*)d_in[8];
    const float* qu_b     = (const float*)d_in[9];
    const float* kvd_w    = (const float*)d_in[10];
    const float* kvd_b    = (const float*)d_in[11];
    const float* ku_w     = (const float*)d_in[12];
    const float* ku_b     = (const float*)d_in[13];
    const float* vu_w     = (const float*)d_in[14];
    const float* vu_b     = (const float*)d_in[15];
    const float* ow       = (const float*)d_in[16];
    const float* ob       = (const float*)d_in[17];
    const float* ln_g     = (const float*)d_in[18];
    const float* ln_b     = (const float*)d_in[19];
    const float* fc_w     = (const float*)d_in[20];
    const float* fc_b     = (const float*)d_in[21];
    float* out = (float*)d_out;

    const int N = in_sizes[2];
    const int E = in_sizes[1] / 2;
    const int G = out_size / OUTD;

    float *p_h0, *p_hl, *p_aggG, *p_h1, *p_cqkv, *p_q, *p_k, *p_v, *p_aggA, *p_h2;
    float *p_deg, *p_mf, *p_den, *p_score, *p_w64, *p_b64;
    unsigned* p_menc;
    cudaGetSymbolAddress((void**)&p_h0, g_h0);
    cudaGetSymbolAddress((void**)&p_hl, g_hl);
    cudaGetSymbolAddress((void**)&p_aggG, g_aggG);
    cudaGetSymbolAddress((void**)&p_h1, g_h1);
    cudaGetSymbolAddress((void**)&p_cqkv, g_cqkv);
    cudaGetSymbolAddress((void**)&p_q, g_q);
    cudaGetSymbolAddress((void**)&p_k, g_k);
    cudaGetSymbolAddress((void**)&p_v, g_v);
    cudaGetSymbolAddress((void**)&p_aggA, g_aggA);
    cudaGetSymbolAddress((void**)&p_h2, g_h2);
    cudaGetSymbolAddress((void**)&p_deg, g_deg);
    cudaGetSymbolAddress((void**)&p_menc, g_menc);
    cudaGetSymbolAddress((void**)&p_mf, g_mf);
    cudaGetSymbolAddress((void**)&p_den, g_den);
    cudaGetSymbolAddress((void**)&p_score, g_score);
    cudaGetSymbolAddress((void**)&p_w64, g_w64);
    cudaGetSymbolAddress((void**)&p_b64, g_b64);

    const int BS = 256;
    const int RPB = 32;
    const int gemm_grid = ceil_div(N, RPB);

    // init
    k_init<<<ceil_div((long long)N * HEADS, BS), BS>>>(p_deg, p_menc, p_den, N);
    k_embed<<<ceil_div((long long)N * 32, BS), BS>>>(x, node_emb, p_h0, p_aggA, N);
    k_deg<<<ceil_div(E, BS), BS>>>(ei, p_deg, E);
    k_dinv<<<ceil_div(N, BS), BS>>>(p_deg, N);

    // GCN
    k_gemm<128, 128, false><<<gemm_grid, 128>>>(p_h0, H, 0, gcn_w, nullptr, p_hl, N, RPB);
    k_selfmsg<<<ceil_div((long long)N * 32, BS), BS>>>(p_hl, p_deg, p_aggG, N);
    k_gcn_scatter<<<ceil_div((long long)E * 32, BS), BS>>>(ei, p_hl, p_deg, p_aggG, E);
    k_bias_relu<<<ceil_div((long long)N * 32, BS), BS>>>(p_aggG, gcn_b, p_h1, N);

    // q/k/v projections
    k_packw<<<ceil_div(H * 64, BS), BS>>>(qd_w, qd_b, kvd_w, kvd_b, p_w64, p_b64);
    k_gemm<128, 64, false><<<gemm_grid, 64>>>(p_h1, H, 0, p_w64, p_b64, p_cqkv, N, RPB);
    k_gemm<32, 128, false><<<gemm_grid, 128>>>(p_cqkv, 64, 0, qu_w, qu_b, p_q, N, RPB);
    k_gemm<32, 128, false><<<gemm_grid, 128>>>(p_cqkv, 64, 32, ku_w, ku_b, p_k, N, RPB);
    k_gemm<32, 128, false><<<gemm_grid, 128>>>(p_cqkv, 64, 32, vu_w, vu_b, p_v, N, RPB);

    // attention softmax over incoming edges
    k_score<<<ceil_div((long long)E * HEADS, BS), BS>>>(ei, p_q, p_k, p_score, p_menc, E);
    k_decode<<<ceil_div((long long)N * HEADS, BS), BS>>>(p_menc, p_mf, N);
    k_exp<<<ceil_div((long long)E * HEADS, BS), BS>>>(ei, p_score, p_mf, p_den, E);
    k_agg<<<ceil_div((long long)E * 32, BS), BS>>>(ei, p_score, p_den, p_v, p_aggA, E);

    // out projection + residual + LN + relu
    k_out_ln<<<gemm_grid, 128>>>(p_aggA, p_h1, ow, ob, ln_g, ln_b, p_h2, N, RPB);

    // pooling + fc (fused, atomic-free)
    k_pool_fc<<<G, 128>>>(p_h2, batch, fc_w, fc_b, out, N);
}

// round 2
// speedup vs baseline: 1.4100x; 1.4100x over previous
#include <cuda_runtime.h>
#include <cuda_bf16.h>
#include <math.h>

// ---------------- problem constants ----------------
#define NMAX 50176
#define EMAX 800000
#define H    128
#define HEADS 8
#define HD   16
#define OUTD 19
#define VMAX 128

// ---------------- scratch ----------------
__device__ float  g_table[VMAX * H];       // (emb @ gcn_w)[vocab]
__device__ float  g_h1[NMAX * H];
__device__ float  g_cqkv[NMAX * 64];
__device__ float  g_q[NMAX * H];           // reused as out-proj temp later
__device__ float  g_k[NMAX * H];
__device__ float  g_v[NMAX * H];
__device__ float  g_aggA[NMAX * H];
__device__ float  g_h2[NMAX * H];
__device__ float  g_w64[H * 64];
__device__ float  g_b64[64];
__device__ int    g_degi[NMAX];
__device__ int    g_rowptr[NMAX];
__device__ int    g_cursor[NMAX];
__device__ int    g_csr[EMAX];
__device__ float2 g_ninfo[NMAX];           // {dinv, token-as-float-bits}

// ---------------- CSR build ----------------
__global__ void k_zero(int* degi, int N) {
    int i = blockIdx.x * blockDim.x + threadIdx.x;
    if (i < N) degi[i] = 0;
}

__global__ void k_count(const int* __restrict__ ei, int* __restrict__ degi, int E) {
    int e = blockIdx.x * blockDim.x + threadIdx.x;
    if (e >= E) return;
    atomicAdd(&degi[ei[E + e]], 1);
}

// single-block exclusive scan (N <= ~50k) + node info pack
__global__ void k_scan(const int* __restrict__ degi, const int* __restrict__ x,
                       int* __restrict__ rowptr, int* __restrict__ cursor,
                       float2* __restrict__ ninfo, int N) {
    __shared__ int sums[1024];
    int t = threadIdx.x;
    int chunk = (N + 1023) >> 10;
    int start = min(t * chunk, N), end = min(start + chunk, N);
    int s = 0;
    for (int i = start; i < end; i++) s += degi[i];
    sums[t] = s;
    __syncthreads();
    for (int off = 1; off < 1024; off <<= 1) {
        int v = (t >= off) ? sums[t - off] : 0;
        __syncthreads();
        sums[t] += v;
        __syncthreads();
    }
    int run = (t == 0) ? 0 : sums[t - 1];
    for (int i = start; i < end; i++) {
        rowptr[i] = run;
        cursor[i] = run;
        float dv = rsqrtf((float)degi[i] + 1.0f);  // +1 self loop
        ninfo[i] = make_float2(dv, __int_as_float(__ldg(x + (size_t)i * 11)));
        run += degi[i];
    }
}

__global__ void k_fill(const int* __restrict__ ei, int* __restrict__ cursor,
                       int* __restrict__ csr, int E) {
    int e = blockIdx.x * blockDim.x + threadIdx.x;
    if (e >= E) return;
    int s = ei[e], d = ei[E + e];
    int pos = atomicAdd(&cursor[d], 1);
    csr[pos] = s;
}

// ---------------- generic GEMM: out = in@W (+b), 8-row register blocking ----------------
template <int IN, int OUT, int ROWS, bool RELU>
__global__ void k_gemm8(const float* __restrict__ in, int in_stride, int in_off,
                        const float* __restrict__ W, const float* __restrict__ B,
                        float* __restrict__ out, int nrows, int rpb) {
    __shared__ float rows_s[ROWS][IN];
    const int tid = threadIdx.x;  // blockDim == OUT
    int r0 = blockIdx.x * rpb, r1 = min(r0 + rpb, nrows);
    float bias = B ? B[tid] : 0.f;
    constexpr int V4 = IN / 4;
    for (int r = r0; r < r1; r += ROWS) {
        __syncthreads();
        for (int i = tid; i < ROWS * V4; i += OUT) {
            int j = i / V4, idx = i % V4;
            float4 val = (r + j < r1)
                ? ((const float4*)(in + (size_t)(r + j) * in_stride + in_off))[idx]
                : make_float4(0.f, 0.f, 0.f, 0.f);
            ((float4*)rows_s[j])[idx] = val;
        }
        __syncthreads();
        float acc[ROWS];
#pragma unroll
        for (int j = 0; j < ROWS; j++) acc[j] = bias;
#pragma unroll 4
        for (int k2 = 0; k2 < IN; k2++) {
            float w = __ldg(W + k2 * OUT + tid);
#pragma unroll
            for (int j = 0; j < ROWS; j++) acc[j] += rows_s[j][k2] * w;
        }
#pragma unroll
        for (int j = 0; j < ROWS; j++)
            if (r + j < r1)
                out[(size_t)(r + j) * OUT + tid] = RELU ? fmaxf(acc[j], 0.f) : acc[j];
    }
}

// pack [qd_w | kvd_w] into one 128x64 weight
__global__ void k_packw(const float* __restrict__ qd_w, const float* __restrict__ qd_b,
                        const float* __restrict__ kvd_w, const float* __restrict__ kvd_b,
                        float* __restrict__ w64, float* __restrict__ b64) {
    int i = blockIdx.x * blockDim.x + threadIdx.x;
    if (i < H * 64) {
        int k2 = i >> 6, c = i & 63;
        w64[i] = (c < 32) ? qd_w[k2 * 32 + c] : kvd_w[k2 * 32 + (c - 32)];
    }
    if (i < 64) b64[i] = (i < 32) ? qd_b[i] : kvd_b[i - 32];
}

// ---------------- GCN aggregation (gather-side, CSR, table-lookup hl) ----------------
__global__ void k_gcn_agg(const int* __restrict__ rowptr, const int* __restrict__ degi,
                          const int* __restrict__ csr, const float2* __restrict__ ninfo,
                          const float* __restrict__ tbl, const float* __restrict__ gb,
                          float* __restrict__ h1, int N) {
    int w = (blockIdx.x * blockDim.x + threadIdx.x) >> 5;
    if (w >= N) return;
    int lane = threadIdx.x & 31;
    int lo = rowptr[w], deg = degi[w];
    float2 di = __ldg(ninfo + w);
    float dinv_d = di.x;
    int tok_d = __float_as_int(di.y);
    // self term folded: acc = dinv_d*tbl[tok_d] + sum_e dinv_s*tbl[tok_s]; out = dinv_d*acc
    float4 t4 = __ldg((const float4*)(tbl + (size_t)tok_d * H) + lane);
    float4 acc = make_float4(dinv_d * t4.x, dinv_d * t4.y, dinv_d * t4.z, dinv_d * t4.w);
    for (int j0 = 0; j0 < deg; j0 += 32) {
        int m = j0 + lane;
        int sj = (m < deg) ? __ldg(csr + lo + m) : 0;
        int cnt = min(32, deg - j0);
#pragma unroll 4
        for (int i = 0; i < cnt; i++) {
            int s = __shfl_sync(~0u, sj, i);
            float2 inf = __ldg(ninfo + s);
            float ds = inf.x;
            int ts = __float_as_int(inf.y);
            float4 r4 = __ldg((const float4*)(tbl + (size_t)ts * H) + lane);
            acc.x += ds * r4.x; acc.y += ds * r4.y;
            acc.z += ds * r4.z; acc.w += ds * r4.w;
        }
    }
    float4 b4 = ((const float4*)gb)[lane];
    float4 o;
    o.x = fmaxf(acc.x * dinv_d + b4.x, 0.f);
    o.y = fmaxf(acc.y * dinv_d + b4.y, 0.f);
    o.z = fmaxf(acc.z * dinv_d + b4.z, 0.f);
    o.w = fmaxf(acc.w * dinv_d + b4.w, 0.f);
    ((float4*)(h1 + (size_t)w * H))[lane] = o;
}

// ---------------- fused q/k/v up-projections ----------------
__global__ void k_qkv(const float* __restrict__ cq,
                      const float* __restrict__ quw, const float* __restrict__ qub,
                      const float* __restrict__ kuw, const float* __restrict__ kub,
                      const float* __restrict__ vuw, const float* __restrict__ vub,
                      float* __restrict__ q, float* __restrict__ k, float* __restrict__ v,
                      int nrows, int rpb) {
    __shared__ float rows_s[4][64];
    const int tid = threadIdx.x;  // 128
    int r0 = blockIdx.x * rpb, r1 = min(r0 + rpb, nrows);
    float bq = qub[tid], bk = kub[tid], bv = vub[tid];
    for (int r = r0; r < r1; r += 4) {
        __syncthreads();
        for (int i = tid; i < 4 * 16; i += 128) {
            int j = i >> 4, idx = i & 15;
            float4 val = (r + j < r1) ? ((const float4*)(cq + (size_t)(r + j) * 64))[idx]
                                      : make_float4(0.f, 0.f, 0.f, 0.f);
            ((float4*)rows_s[j])[idx] = val;
        }
        __syncthreads();
        float aq[4], ak[4], av[4];
#pragma unroll
        for (int j = 0; j < 4; j++) { aq[j] = bq; ak[j] = bk; av[j] = bv; }
#pragma unroll 4
        for (int kk = 0; kk < 32; kk++) {
            float wq = __ldg(quw + kk * 128 + tid);
            float wk = __ldg(kuw + kk * 128 + tid);
            float wv = __ldg(vuw + kk * 128 + tid);
#pragma unroll
            for (int j = 0; j < 4; j++) {
                float xq = rows_s[j][kk], xkv = rows_s[j][kk + 32];
                aq[j] += xq * wq; ak[j] += xkv * wk; av[j] += xkv * wv;
            }
        }
#pragma unroll
        for (int j = 0; j < 4; j++) {
            if (r + j < r1) {
                q[(size_t)(r + j) * H + tid] = aq[j];
                k[(size_t)(r + j) * H + tid] = ak[j];
                v[(size_t)(r + j) * H + tid] = av[j];
            }
        }
    }
}

// ---------------- fused attention: one pass, gather-side, no atomics ----------------
// softmax shift-invariance: agg = sum(e^s * v) / sum(e^s)  (scores are O(1e-8) here)
__global__ void k_attn(const int* __restrict__ rowptr, const int* __restrict__ degi,
                       const int* __restrict__ csr,
                       const float* __restrict__ q, const float* __restrict__ kk,
                       const float* __restrict__ v, float* __restrict__ agg, int N) {
    int w = (blockIdx.x * blockDim.x + threadIdx.x) >> 5;
    if (w >= N) return;
    int lane = threadIdx.x & 31;
    int lo = rowptr[w], deg = degi[w];
    float4 q4 = ((const float4*)(q + (size_t)w * H))[lane];
    q4.x *= 0.25f; q4.y *= 0.25f; q4.z *= 0.25f; q4.w *= 0.25f;  // 1/sqrt(16)
    float4 acc = make_float4(0.f, 0.f, 0.f, 0.f);
    float den = 0.f;
    for (int j0 = 0; j0 < deg; j0 += 32) {
        int m = j0 + lane;
        int sj = (m < deg) ? __ldg(csr + lo + m) : 0;
        int cnt = min(32, deg - j0);
#pragma unroll 4
        for (int i = 0; i < cnt; i++) {
            int s = __shfl_sync(~0u, sj, i);
            float4 k4 = __ldg((const float4*)(kk + (size_t)s * H) + lane);
            float part = q4.x * k4.x + q4.y * k4.y + q4.z * k4.z + q4.w * k4.w;
            part += __shfl_xor_sync(~0u, part, 1);
            part += __shfl_xor_sync(~0u, part, 2);  // per-head (quad) dot
            float ex = __expf(part);
            float4 v4 = __ldg((const float4*)(v + (size_t)s * H) + lane);
            den += ex;
            acc.x += ex * v4.x; acc.y += ex * v4.y;
            acc.z += ex * v4.z; acc.w += ex * v4.w;
        }
    }
    float inv = 1.f / fmaxf(den, 1e-16f);
    float4 o = make_float4(acc.x * inv, acc.y * inv, acc.z * inv, acc.w * inv);
    ((float4*)(agg + (size_t)w * H))[lane] = o;
}

// ---------------- residual + LayerNorm + relu ----------------
__global__ void k_ln(const float* __restrict__ a, const float* __restrict__ res,
                     const float* __restrict__ lg, const float* __restrict__ lb,
                     float* __restrict__ o, int N) {
    int r = blockIdx.x;
    int tid = threadIdx.x;  // 128
    __shared__ float red[8];
    float t = a[(size_t)r * H + tid] + res[(size_t)r * H + tid];
    float s1 = t;
    for (int o2 = 16; o2 > 0; o2 >>= 1) s1 += __shfl_down_sync(~0u, s1, o2);
    if ((tid & 31) == 0) red[tid >> 5] = s1;
    __syncthreads();
    float mu = (red[0] + red[1] + red[2] + red[3]) * (1.f / 128.f);
    float dv = (t - mu) * (t - mu);
    for (int o2 = 16; o2 > 0; o2 >>= 1) dv += __shfl_down_sync(~0u, dv, o2);
    if ((tid & 31) == 0) red[4 + (tid >> 5)] = dv;
    __syncthreads();
    float var = (red[4] + red[5] + red[6] + red[7]) * (1.f / 128.f);
    o[(size_t)r * H + tid] =
        fmaxf((t - mu) * rsqrtf(var + 1e-5f) * lg[tid] + lb[tid], 0.f);
}

// ---------------- fused pooling + final FC ----------------
__device__ __forceinline__ int lower_bound(const int* __restrict__ a, int n, int key) {
    int lo = 0, hi = n;
    while (lo < hi) {
        int mid = (lo + hi) >> 1;
        if (a[mid] < key) lo = mid + 1; else hi = mid;
    }
    return lo;
}

__global__ void k_pool_fc(const float* __restrict__ h2, const int* __restrict__ batch,
                          const float* __restrict__ fc_w, const float* __restrict__ fc_b,
                          float* __restrict__ out, int N) {
    int g = blockIdx.x;
    int tid = threadIdx.x;  // 128
    __shared__ float pool[H];
    int lo = lower_bound(batch, N, g);
    int hi = lower_bound(batch, N, g + 1);
    float acc = 0.f;
    for (int n = lo; n < hi; n++) acc += h2[(size_t)n * H + tid];
    pool[tid] = acc;
    __syncthreads();
    if (tid < OUTD) {
        float o = fc_b[tid];
#pragma unroll 16
        for (int c = 0; c < H; c++) o += pool[c] * __ldg(fc_w + c * OUTD + tid);
        out[(size_t)g * OUTD + tid] = o;
    }
}

// ---------------- host ----------------
static inline int ceil_div(long long a, int b) { return (int)((a + b - 1) / b); }

extern "C" void kernel_launch(void* const* d_in, const int* in_sizes, int n_in,
                              void* d_out, int out_size) {
    const int*   x        = (const int*)d_in[0];
    const int*   ei       = (const int*)d_in[1];
    const int*   batch    = (const int*)d_in[2];
    const float* node_emb = (const float*)d_in[3];
    const float* gcn_w    = (const float*)d_in[4];
    const float* gcn_b    = (const float*)d_in[5];
    const float* qd_w     = (const float*)d_in[6];
    const float* qd_b     = (const float*)d_in[7];
    const float* qu_w     = (const float*)d_in[8];
    const float* qu_b     = (const float*)d_in[9];
    const float* kvd_w    = (const float*)d_in[10];
    const float* kvd_b    = (const float*)d_in[11];
    const float* ku_w     = (const float*)d_in[12];
    const float* ku_b     = (const float*)d_in[13];
    const float* vu_w     = (const float*)d_in[14];
    const float* vu_b     = (const float*)d_in[15];
    const float* ow       = (const float*)d_in[16];
    const float* ob       = (const float*)d_in[17];
    const float* ln_g     = (const float*)d_in[18];
    const float* ln_b     = (const float*)d_in[19];
    const float* fc_w     = (const float*)d_in[20];
    const float* fc_b     = (const float*)d_in[21];
    float* out = (float*)d_out;

    const int N = in_sizes[2];
    const int E = in_sizes[1] / 2;
    const int G = out_size / OUTD;
    const int V = in_sizes[3] / H;

    float *p_table, *p_h1, *p_cqkv, *p_q, *p_k, *p_v, *p_aggA, *p_h2, *p_w64, *p_b64;
    int *p_degi, *p_rowptr, *p_cursor, *p_csr;
    float2* p_ninfo;
    cudaGetSymbolAddress((void**)&p_table, g_table);
    cudaGetSymbolAddress((void**)&p_h1, g_h1);
    cudaGetSymbolAddress((void**)&p_cqkv, g_cqkv);
    cudaGetSymbolAddress((void**)&p_q, g_q);
    cudaGetSymbolAddress((void**)&p_k, g_k);
    cudaGetSymbolAddress((void**)&p_v, g_v);
    cudaGetSymbolAddress((void**)&p_aggA, g_aggA);
    cudaGetSymbolAddress((void**)&p_h2, g_h2);
    cudaGetSymbolAddress((void**)&p_w64, g_w64);
    cudaGetSymbolAddress((void**)&p_b64, g_b64);
    cudaGetSymbolAddress((void**)&p_degi, g_degi);
    cudaGetSymbolAddress((void**)&p_rowptr, g_rowptr);
    cudaGetSymbolAddress((void**)&p_cursor, g_cursor);
    cudaGetSymbolAddress((void**)&p_csr, g_csr);
    cudaGetSymbolAddress((void**)&p_ninfo, g_ninfo);

    const int BS = 256;
    const int RPB = 32;
    const int gemm_grid = ceil_div(N, RPB);
    const int warp_grid = ceil_div((long long)N * 32, BS);

    // CSR build
    k_zero<<<ceil_div(N, BS), BS>>>(p_degi, N);
    k_count<<<ceil_div(E, BS), BS>>>(ei, p_degi, E);
    k_scan<<<1, 1024>>>(p_degi, x, p_rowptr, p_cursor, p_ninfo, N);
    k_fill<<<ceil_div(E, BS), BS>>>(ei, p_cursor, p_csr, E);

    // vocab table = emb @ gcn_w  (tiny GEMM, replaces full GCN GEMM)
    k_gemm8<128, 128, 8, false><<<ceil_div(V, 8), 128>>>(node_emb, H, 0, gcn_w, nullptr,
                                                         p_table, V, 8);
    // GCN aggregation (fused norm + bias + relu)
    k_gcn_agg<<<warp_grid, BS>>>(p_rowptr, p_degi, p_csr, p_ninfo, p_table, gcn_b, p_h1, N);

    // down projection (packed q/kv)
    k_packw<<<ceil_div(H * 64, BS), BS>>>(qd_w, qd_b, kvd_w, kvd_b, p_w64, p_b64);
    k_gemm8<128, 64, 8, false><<<gemm_grid, 64>>>(p_h1, H, 0, p_w64, p_b64, p_cqkv, N, RPB);

    // fused q/k/v up projections
    k_qkv<<<gemm_grid, 128>>>(p_cqkv, qu_w, qu_b, ku_w, ku_b, vu_w, vu_b,
                              p_q, p_k, p_v, N, RPB);

    // fused single-pass attention
    k_attn<<<warp_grid, BS>>>(p_rowptr, p_degi, p_csr, p_q, p_k, p_v, p_aggA, N);

    // output projection (reuse g_q as temp), residual+LN+relu
    k_gemm8<128, 128, 8, false><<<gemm_grid, 128>>>(p_aggA, H, 0, ow, ob, p_q, N, RPB);
    k_ln<<<N, 128>>>(p_q, p_h1, ln_g, ln_b, p_h2, N);

    // pooling + fc
    k_pool_fc<<<G, 128>>>(p_h2, batch, fc_w, fc_b, out, N);
}

// round 3
// speedup vs baseline: 1.5066x; 1.0685x over previous
#include <cuda_runtime.h>
#include <cuda_bf16.h>
#include <math.h>

// ---------------- problem constants ----------------
#define NMAX 50176
#define EMAX 800000
#define H    128
#define HEADS 8
#define HD   16
#define OUTD 19
#define VMAX 128
#define CHUNK 256   // scan chunk

// ---------------- scratch ----------------
__device__ float  g_table[VMAX * H];       // (emb @ gcn_w)[vocab]
__device__ float  g_h1[NMAX * H];
__device__ float  g_cqkv[NMAX * 64];
__device__ float  g_q[NMAX * H];           // q, later reused as out-proj temp
__device__ float  g_qk[NMAX * 256];        // absorbed q@ku_w per head
__device__ float  g_qb[NMAX * 8];          // per-head ku_b score bias
__device__ float  g_aggcn[NMAX * 256];     // normalized latent aggregation
__device__ float  g_flag[NMAX];            // 1 if deg>0
__device__ float  g_agg[NMAX * H];
__device__ float  g_h2[NMAX * H];
__device__ float  g_w64[H * 64];
__device__ float  g_b64[64];
__device__ float  g_kuT[H * 32];           // ku_w transposed * scale
__device__ int    g_degi[NMAX];
__device__ int    g_rowptr[NMAX];
__device__ int    g_cursor[NMAX];
__device__ int    g_csr[EMAX];
__device__ int    g_psum[256];
__device__ float2 g_ninfo[NMAX];           // {dinv, token bits}

// ---------------- CSR build ----------------
__global__ void k_zero(int* degi, int N) {
    int i = blockIdx.x * blockDim.x + threadIdx.x;
    if (i < N) degi[i] = 0;
}

__global__ void k_count(const int* __restrict__ ei, int* __restrict__ degi, int E) {
    int e = blockIdx.x * blockDim.x + threadIdx.x;
    if (e >= E) return;
    atomicAdd(&degi[ei[E + e]], 1);
}

__global__ void k_psumk(const int* __restrict__ degi, int* __restrict__ psum, int N) {
    __shared__ int s[CHUNK];
    int i = blockIdx.x * CHUNK + threadIdx.x;
    s[threadIdx.x] = (i < N) ? degi[i] : 0;
    __syncthreads();
    for (int off = 128; off > 0; off >>= 1) {
        if (threadIdx.x < off) s[threadIdx.x] += s[threadIdx.x + off];
        __syncthreads();
    }
    if (threadIdx.x == 0) psum[blockIdx.x] = s[0];
}

__global__ void k_scanblk(int* psum, int nb) {
    __shared__ int s[256];
    int t = threadIdx.x;
    s[t] = (t < nb) ? psum[t] : 0;
    __syncthreads();
    for (int off = 1; off < 256; off <<= 1) {
        int v = (t >= off) ? s[t - off] : 0;
        __syncthreads();
        s[t] += v;
        __syncthreads();
    }
    if (t < nb) psum[t] = (t == 0) ? 0 : s[t - 1];  // exclusive
}

__global__ void k_write(const int* __restrict__ degi, const int* __restrict__ psum,
                        const int* __restrict__ x, int* __restrict__ rowptr,
                        int* __restrict__ cursor, float2* __restrict__ ninfo, int N) {
    __shared__ int s[CHUNK];
    int i = blockIdx.x * CHUNK + threadIdx.x;
    int t = threadIdx.x;
    int d = (i < N) ? degi[i] : 0;
    s[t] = d;
    __syncthreads();
    for (int off = 1; off < CHUNK; off <<= 1) {
        int v = (t >= off) ? s[t - off] : 0;
        __syncthreads();
        s[t] += v;
        __syncthreads();
    }
    if (i < N) {
        int rp = psum[blockIdx.x] + s[t] - d;  // exclusive
        rowptr[i] = rp;
        cursor[i] = rp;
        float dv = rsqrtf((float)d + 1.0f);
        ninfo[i] = make_float2(dv, __int_as_float(__ldg(x + (size_t)i * 11)));
    }
}

__global__ void k_fill(const int* __restrict__ ei, int* __restrict__ cursor,
                       int* __restrict__ csr, int E) {
    int e = blockIdx.x * blockDim.x + threadIdx.x;
    if (e >= E) return;
    int s = ei[e], d = ei[E + e];
    int pos = atomicAdd(&cursor[d], 1);
    csr[pos] = s;
}

// ---------------- generic GEMM: out = in@W (+b), 8-row register blocking ----------------
template <int IN, int OUT, int ROWS, bool RELU>
__global__ void k_gemm8(const float* __restrict__ in, int in_stride, int in_off,
                        const float* __restrict__ W, const float* __restrict__ B,
                        float* __restrict__ out, int nrows, int rpb) {
    __shared__ float rows_s[ROWS][IN];
    const int tid = threadIdx.x;  // blockDim == OUT
    int r0 = blockIdx.x * rpb, r1 = min(r0 + rpb, nrows);
    float bias = B ? B[tid] : 0.f;
    constexpr int V4 = IN / 4;
    for (int r = r0; r < r1; r += ROWS) {
        __syncthreads();
        for (int i = tid; i < ROWS * V4; i += OUT) {
            int j = i / V4, idx = i % V4;
            float4 val = (r + j < r1)
                ? ((const float4*)(in + (size_t)(r + j) * in_stride + in_off))[idx]
                : make_float4(0.f, 0.f, 0.f, 0.f);
            ((float4*)rows_s[j])[idx] = val;
        }
        __syncthreads();
        float acc[ROWS];
#pragma unroll
        for (int j = 0; j < ROWS; j++) acc[j] = bias;
#pragma unroll 4
        for (int k2 = 0; k2 < IN; k2++) {
            float w = __ldg(W + k2 * OUT + tid);
#pragma unroll
            for (int j = 0; j < ROWS; j++) acc[j] += rows_s[j][k2] * w;
        }
#pragma unroll
        for (int j = 0; j < ROWS; j++)
            if (r + j < r1)
                out[(size_t)(r + j) * OUT + tid] = RELU ? fmaxf(acc[j], 0.f) : acc[j];
    }
}

// pack [qd_w | kvd_w]; transpose+scale ku_w
__global__ void k_prep(const float* __restrict__ qd_w, const float* __restrict__ qd_b,
                       const float* __restrict__ kvd_w, const float* __restrict__ kvd_b,
                       const float* __restrict__ ku_w,
                       float* __restrict__ w64, float* __restrict__ b64,
                       float* __restrict__ kuT) {
    int i = blockIdx.x * blockDim.x + threadIdx.x;
    if (i < H * 64) {
        int k2 = i >> 6, c = i & 63;
        w64[i] = (c < 32) ? qd_w[k2 * 32 + c] : kvd_w[k2 * 32 + (c - 32)];
    }
    if (i < 64) b64[i] = (i < 32) ? qd_b[i] : kvd_b[i - 32];
    if (i < H * 32) {
        int hj = i >> 5, c = i & 31;  // kuT[hj][c] = 0.25*ku_w[c][hj]
        kuT[i] = 0.25f * ku_w[c * H + hj];
    }
}

// ---------------- GCN aggregation (gather-side, CSR, table-lookup hl) ----------------
__global__ void k_gcn_agg(const int* __restrict__ rowptr, const int* __restrict__ degi,
                          const int* __restrict__ csr, const float2* __restrict__ ninfo,
                          const float* __restrict__ tbl, const float* __restrict__ gb,
                          float* __restrict__ h1, int N) {
    int w = (blockIdx.x * blockDim.x + threadIdx.x) >> 5;
    if (w >= N) return;
    int lane = threadIdx.x & 31;
    int lo = rowptr[w], deg = degi[w];
    float2 di = __ldg(ninfo + w);
    float dinv_d = di.x;
    int tok_d = __float_as_int(di.y);
    float4 t4 = __ldg((const float4*)(tbl + (size_t)tok_d * H) + lane);
    float4 acc = make_float4(dinv_d * t4.x, dinv_d * t4.y, dinv_d * t4.z, dinv_d * t4.w);
    for (int j0 = 0; j0 < deg; j0 += 32) {
        int m = j0 + lane;
        int sj = (m < deg) ? __ldg(csr + lo + m) : 0;
        int cnt = min(32, deg - j0);
#pragma unroll 4
        for (int i = 0; i < cnt; i++) {
            int s = __shfl_sync(~0u, sj, i);
            float2 inf = __ldg(ninfo + s);
            float ds = inf.x;
            int ts = __float_as_int(inf.y);
            float4 r4 = __ldg((const float4*)(tbl + (size_t)ts * H) + lane);
            acc.x += ds * r4.x; acc.y += ds * r4.y;
            acc.z += ds * r4.z; acc.w += ds * r4.w;
        }
    }
    float4 b4 = ((const float4*)gb)[lane];
    float4 o;
    o.x = fmaxf(acc.x * dinv_d + b4.x, 0.f);
    o.y = fmaxf(acc.y * dinv_d + b4.y, 0.f);
    o.z = fmaxf(acc.z * dinv_d + b4.z, 0.f);
    o.w = fmaxf(acc.w * dinv_d + b4.w, 0.f);
    ((float4*)(h1 + (size_t)w * H))[lane] = o;
}

// ---------------- MLA absorption: qk[n][h*32+c] = 0.25 * sum_j q[n][hj]*ku_w[c][hj] ----------------
__global__ void k_qkabsorb(const float* __restrict__ q, const float* __restrict__ kuT,
                           const float* __restrict__ ku_b,
                           float* __restrict__ qk, float* __restrict__ qb,
                           int nrows, int rpb) {
    __shared__ float qs[4][H];
    const int t = threadIdx.x;  // 256: h = t>>5, c = t&31
    const int h = t >> 5, c = t & 31;
    // fixed weights per thread
    float w[HD];
#pragma unroll
    for (int j = 0; j < HD; j++) w[j] = __ldg(kuT + (h * HD + j) * 32 + c);
    float kb[HD];
    if (t < 8) {
#pragma unroll
        for (int j = 0; j < HD; j++) kb[j] = __ldg(ku_b + t * HD + j);
    }
    int r0 = blockIdx.x * rpb, r1 = min(r0 + rpb, nrows);
    for (int r = r0; r < r1; r += 4) {
        __syncthreads();
        for (int i = t; i < 4 * 32; i += 256) {
            int rj = i >> 5, idx = i & 31;
            float4 val = (r + rj < r1) ? ((const float4*)(q + (size_t)(r + rj) * H))[idx]
                                       : make_float4(0.f, 0.f, 0.f, 0.f);
            ((float4*)qs[rj])[idx] = val;
        }
        __syncthreads();
#pragma unroll
        for (int rj = 0; rj < 4; rj++) {
            if (r + rj >= r1) break;
            float acc = 0.f;
#pragma unroll
            for (int j = 0; j < HD; j++) acc += qs[rj][h * HD + j] * w[j];
            qk[(size_t)(r + rj) * 256 + t] = acc;
        }
        if (t < 8) {
#pragma unroll
            for (int rj = 0; rj < 4; rj++) {
                if (r + rj >= r1) break;
                float acc = 0.f;
#pragma unroll
                for (int j = 0; j < HD; j++) acc += qs[rj][t * HD + j] * kb[j];
                qb[(size_t)(r + rj) * 8 + t] = 0.25f * acc;
            }
        }
    }
}

// ---------------- fused attention in latent space ----------------
// warp per dst; 4 edge-groups x 8 lanes; lane owns c-quad (l&7)
__global__ void __launch_bounds__(256) k_attn2(
        const int* __restrict__ rowptr, const int* __restrict__ degi,
        const int* __restrict__ csr, const float* __restrict__ cqkv,
        const float* __restrict__ qk, const float* __restrict__ qb,
        float* __restrict__ aggcn, float* __restrict__ flag, int N) {
    int w = (blockIdx.x * blockDim.x + threadIdx.x) >> 5;
    if (w >= N) return;
    int lane = threadIdx.x & 31;
    int g = lane >> 3, cq = lane & 7;
    int lo = rowptr[w], deg = degi[w];

    float4 qk4[HEADS];
#pragma unroll
    for (int h = 0; h < HEADS; h++)
        qk4[h] = __ldg((const float4*)(qk + (size_t)w * 256 + h * 32) + cq);
    float qbr[HEADS];
    {
        float4 a = __ldg((const float4*)(qb + (size_t)w * 8));
        float4 b = __ldg((const float4*)(qb + (size_t)w * 8) + 1);
        qbr[0] = a.x; qbr[1] = a.y; qbr[2] = a.z; qbr[3] = a.w;
        qbr[4] = b.x; qbr[5] = b.y; qbr[6] = b.z; qbr[7] = b.w;
    }
    float den[HEADS];
    float4 acc[HEADS];
#pragma unroll
    for (int h = 0; h < HEADS; h++) { den[h] = 0.f; acc[h] = make_float4(0.f, 0.f, 0.f, 0.f); }

    for (int j0 = 0; j0 < deg; j0 += 4) {
        int m = j0 + g;
        bool act = (m < deg);
        int s = act ? __ldg(csr + lo + m) : 0;
        float4 c4 = act ? __ldg((const float4*)(cqkv + (size_t)s * 64 + 32) + cq)
                        : make_float4(0.f, 0.f, 0.f, 0.f);
        float p[HEADS];
#pragma unroll
        for (int h = 0; h < HEADS; h++)
            p[h] = qk4[h].x * c4.x + qk4[h].y * c4.y + qk4[h].z * c4.z + qk4[h].w * c4.w;
#pragma unroll
        for (int st = 1; st <= 4; st <<= 1)
#pragma unroll
            for (int h = 0; h < HEADS; h++) p[h] += __shfl_xor_sync(~0u, p[h], st);
#pragma unroll
        for (int h = 0; h < HEADS; h++) {
            float ex = act ? __expf(p[h] + qbr[h]) : 0.f;
            den[h] += ex;
            acc[h].x += ex * c4.x; acc[h].y += ex * c4.y;
            acc[h].z += ex * c4.z; acc[h].w += ex * c4.w;
        }
    }
    // cross-group reduce (xor 8, 16)
#pragma unroll
    for (int st = 8; st <= 16; st <<= 1)
#pragma unroll
        for (int h = 0; h < HEADS; h++) {
            den[h] += __shfl_xor_sync(~0u, den[h], st);
            acc[h].x += __shfl_xor_sync(~0u, acc[h].x, st);
            acc[h].y += __shfl_xor_sync(~0u, acc[h].y, st);
            acc[h].z += __shfl_xor_sync(~0u, acc[h].z, st);
            acc[h].w += __shfl_xor_sync(~0u, acc[h].w, st);
        }
    if (g == 0) {
#pragma unroll
        for (int h = 0; h < HEADS; h++) {
            float inv = (deg > 0) ? 1.f / fmaxf(den[h], 1e-16f) : 0.f;
            float4 o = make_float4(acc[h].x * inv, acc[h].y * inv,
                                   acc[h].z * inv, acc[h].w * inv);
            ((float4*)(aggcn + (size_t)w * 256 + h * 32))[cq] = o;
        }
        if (lane == 0) flag[w] = (deg > 0) ? 1.f : 0.f;
    }
}

// ---------------- v up-projection on aggregated latent ----------------
__global__ void k_vup(const float* __restrict__ aggcn, const float* __restrict__ flag,
                      const float* __restrict__ vu_w, const float* __restrict__ vu_b,
                      float* __restrict__ agg, int nrows, int rpb) {
    __shared__ float as[4][256];
    __shared__ float fl[4];
    const int t = threadIdx.x;  // 128: h = t>>4, j = t&15
    const int h = t >> 4;
    float w[32];
#pragma unroll
    for (int c = 0; c < 32; c++) w[c] = __ldg(vu_w + c * H + t);  // vu_w[c][h*16+j]
    float vb = __ldg(vu_b + t);
    int r0 = blockIdx.x * rpb, r1 = min(r0 + rpb, nrows);
    for (int r = r0; r < r1; r += 4) {
        __syncthreads();
        for (int i = t; i < 4 * 64; i += 128) {
            int rj = i >> 6, idx = i & 63;
            float4 val = (r + rj < r1) ? ((const float4*)(aggcn + (size_t)(r + rj) * 256))[idx]
                                       : make_float4(0.f, 0.f, 0.f, 0.f);
            ((float4*)as[rj])[idx] = val;
        }
        if (t < 4) fl[t] = (r + t < r1) ? flag[r + t] : 0.f;
        __syncthreads();
#pragma unroll
        for (int rj = 0; rj < 4; rj++) {
            if (r + rj >= r1) break;
            float accv = fl[rj] * vb;
#pragma unroll
            for (int c = 0; c < 32; c++) accv += as[rj][h * 32 + c] * w[c];
            agg[(size_t)(r + rj) * H + t] = accv;
        }
    }
}

// ---------------- residual + LayerNorm + relu ----------------
__global__ void k_ln(const float* __restrict__ a, const float* __restrict__ res,
                     const float* __restrict__ lg, const float* __restrict__ lb,
                     float* __restrict__ o, int N) {
    int r = blockIdx.x;
    int tid = threadIdx.x;  // 128
    __shared__ float red[8];
    float t = a[(size_t)r * H + tid] + res[(size_t)r * H + tid];
    float s1 = t;
    for (int o2 = 16; o2 > 0; o2 >>= 1) s1 += __shfl_down_sync(~0u, s1, o2);
    if ((tid & 31) == 0) red[tid >> 5] = s1;
    __syncthreads();
    float mu = (red[0] + red[1] + red[2] + red[3]) * (1.f / 128.f);
    float dv = (t - mu) * (t - mu);
    for (int o2 = 16; o2 > 0; o2 >>= 1) dv += __shfl_down_sync(~0u, dv, o2);
    if ((tid & 31) == 0) red[4 + (tid >> 5)] = dv;
    __syncthreads();
    float var = (red[4] + red[5] + red[6] + red[7]) * (1.f / 128.f);
    o[(size_t)r * H + tid] =
        fmaxf((t - mu) * rsqrtf(var + 1e-5f) * lg[tid] + lb[tid], 0.f);
}

// ---------------- fused pooling + final FC ----------------
__device__ __forceinline__ int lower_bound(const int* __restrict__ a, int n, int key) {
    int lo = 0, hi = n;
    while (lo < hi) {
        int mid = (lo + hi) >> 1;
        if (a[mid] < key) lo = mid + 1; else hi = mid;
    }
    return lo;
}

__global__ void k_pool_fc(const float* __restrict__ h2, const int* __restrict__ batch,
                          const float* __restrict__ fc_w, const float* __restrict__ fc_b,
                          float* __restrict__ out, int N) {
    int g = blockIdx.x;
    int tid = threadIdx.x;  // 128
    __shared__ float pool[H];
    int lo = lower_bound(batch, N, g);
    int hi = lower_bound(batch, N, g + 1);
    float acc = 0.f;
    for (int n = lo; n < hi; n++) acc += h2[(size_t)n * H + tid];
    pool[tid] = acc;
    __syncthreads();
    if (tid < OUTD) {
        float o = fc_b[tid];
#pragma unroll 16
        for (int c = 0; c < H; c++) o += pool[c] * __ldg(fc_w + c * OUTD + tid);
        out[(size_t)g * OUTD + tid] = o;
    }
}

// ---------------- host ----------------
static inline int ceil_div(long long a, int b) { return (int)((a + b - 1) / b); }

extern "C" void kernel_launch(void* const* d_in, const int* in_sizes, int n_in,
                              void* d_out, int out_size) {
    const int*   x        = (const int*)d_in[0];
    const int*   ei       = (const int*)d_in[1];
    const int*   batch    = (const int*)d_in[2];
    const float* node_emb = (const float*)d_in[3];
    const float* gcn_w    = (const float*)d_in[4];
    const float* gcn_b    = (const float*)d_in[5];
    const float* qd_w     = (const float*)d_in[6];
    const float* qd_b     = (const float*)d_in[7];
    const float* qu_w     = (const float*)d_in[8];
    const float* qu_b     = (const float*)d_in[9];
    const float* kvd_w    = (const float*)d_in[10];
    const float* kvd_b    = (const float*)d_in[11];
    const float* ku_w     = (const float*)d_in[12];
    const float* ku_b     = (const float*)d_in[13];
    const float* vu_w     = (const float*)d_in[14];
    const float* vu_b     = (const float*)d_in[15];
    const float* ow       = (const float*)d_in[16];
    const float* ob       = (const float*)d_in[17];
    const float* ln_g     = (const float*)d_in[18];
    const float* ln_b     = (const float*)d_in[19];
    const float* fc_w     = (const float*)d_in[20];
    const float* fc_b     = (const float*)d_in[21];
    float* out = (float*)d_out;

    const int N = in_sizes[2];
    const int E = in_sizes[1] / 2;
    const int G = out_size / OUTD;
    const int V = in_sizes[3] / H;

    float *p_table, *p_h1, *p_cqkv, *p_q, *p_qk, *p_qb, *p_aggcn, *p_flag, *p_agg, *p_h2;
    float *p_w64, *p_b64, *p_kuT;
    int *p_degi, *p_rowptr, *p_cursor, *p_csr, *p_psum;
    float2* p_ninfo;
    cudaGetSymbolAddress((void**)&p_table, g_table);
    cudaGetSymbolAddress((void**)&p_h1, g_h1);
    cudaGetSymbolAddress((void**)&p_cqkv, g_cqkv);
    cudaGetSymbolAddress((void**)&p_q, g_q);
    cudaGetSymbolAddress((void**)&p_qk, g_qk);
    cudaGetSymbolAddress((void**)&p_qb, g_qb);
    cudaGetSymbolAddress((void**)&p_aggcn, g_aggcn);
    cudaGetSymbolAddress((void**)&p_flag, g_flag);
    cudaGetSymbolAddress((void**)&p_agg, g_agg);
    cudaGetSymbolAddress((void**)&p_h2, g_h2);
    cudaGetSymbolAddress((void**)&p_w64, g_w64);
    cudaGetSymbolAddress((void**)&p_b64, g_b64);
    cudaGetSymbolAddress((void**)&p_kuT, g_kuT);
    cudaGetSymbolAddress((void**)&p_degi, g_degi);
    cudaGetSymbolAddress((void**)&p_rowptr, g_rowptr);
    cudaGetSymbolAddress((void**)&p_cursor, g_cursor);
    cudaGetSymbolAddress((void**)&p_csr, g_csr);
    cudaGetSymbolAddress((void**)&p_psum, g_psum);
    cudaGetSymbolAddress((void**)&p_ninfo, g_ninfo);

    const int BS = 256;
    const int RPB = 32;
    const int gemm_grid = ceil_div(N, RPB);
    const int warp_grid = ceil_div((long long)N * 32, BS);
    const int nblk = ceil_div(N, CHUNK);

    // CSR build (parallel scan)
    k_zero<<<ceil_div(N, BS), BS>>>(p_degi, N);
    k_count<<<ceil_div(E, BS), BS>>>(ei, p_degi, E);
    k_psumk<<<nblk, CHUNK>>>(p_degi, p_psum, N);
    k_scanblk<<<1, 256>>>(p_psum, nblk);
    k_write<<<nblk, CHUNK>>>(p_degi, p_psum, x, p_rowptr, p_cursor, p_ninfo, N);
    k_fill<<<ceil_div(E, BS), BS>>>(ei, p_cursor, p_csr, E);

    // weight prep: vocab table, packed down-proj, scaled kuT
    k_gemm8<128, 128, 8, false><<<ceil_div(V, 8), 128>>>(node_emb, H, 0, gcn_w, nullptr,
                                                         p_table, V, 8);
    k_prep<<<ceil_div(H * 64, BS), BS>>>(qd_w, qd_b, kvd_w, kvd_b, ku_w, p_w64, p_b64, p_kuT);

    // GCN aggregation (fused norm + bias + relu)
    k_gcn_agg<<<warp_grid, BS>>>(p_rowptr, p_degi, p_csr, p_ninfo, p_table, gcn_b, p_h1, N);

    // down projection (packed q/kv latents)
    k_gemm8<128, 64, 8, false><<<gemm_grid, 64>>>(p_h1, H, 0, p_w64, p_b64, p_cqkv, N, RPB);

    // q up-projection + ku_w absorption
    k_gemm8<32, 128, 8, false><<<gemm_grid, 128>>>(p_cqkv, 64, 0, qu_w, qu_b, p_q, N, RPB);
    k_qkabsorb<<<gemm_grid, 256>>>(p_q, p_kuT, ku_b, p_qk, p_qb, N, RPB);

    // fused latent-space attention (128B/edge instead of 1KB/edge)
    k_attn2<<<warp_grid, BS>>>(p_rowptr, p_degi, p_csr, p_cqkv, p_qk, p_qb,
                               p_aggcn, p_flag, N);

    // v up-projection on aggregated latents
    k_vup<<<gemm_grid, 128>>>(p_aggcn, p_flag, vu_w, vu_b, p_agg, N, RPB);

    // output projection (reuse g_q as temp), residual+LN+relu
    k_gemm8<128, 128, 8, false><<<gemm_grid, 128>>>(p_agg, H, 0, ow, ob, p_q, N, RPB);
    k_ln<<<N, 128>>>(p_q, p_h1, ln_g, ln_b, p_h2, N);

    // pooling + fc
    k_pool_fc<<<G, 128>>>(p_h2, batch, fc_w, fc_b, out, N);
}